// round 13
// baseline (speedup 1.0000x reference)
#include <cuda_runtime.h>
#include <cuda_bf16.h>
#include <stdint.h>

#define NROWS 131072
#define DDIM  64
#define KPROT 512
#define TM    128
#define TN    64
#define NTILES (KPROT / TN)   // 8

// ---- shared memory layout (bytes) ----
#define OFF_AHI   0        // 16KB  A hi (128 rows x 128B, swizzled)
#define OFF_ALO   16384    // 16KB  A lo
#define OFF_WB    32768    // 2 x 16KB W double buffer (hi 8KB + lo 8KB each)
#define OFF_W2    65536    // 512 floats (2KB)
#define OFF_RMIN  67584    // 128 ints
#define OFF_CMIN  68096    // 512 ints (2KB)
#define SMEM_TOTAL 70144

#define XN1_OFF   ((size_t)NROWS*DDIM)              // 8388608
#define PROTO_OFF ((size_t)2*NROWS*DDIM)            // 16777216
#define SCAL_OFF  (PROTO_OFF + (size_t)NROWS*KPROT) // 83886080

__device__ int          g_rowmin[NROWS];
__device__ int          g_colmin[KPROT];
__device__ float        g_partial[128];
__device__ float        g_w2[KPROT];
__device__ unsigned int g_ctr;
__device__ __align__(16) unsigned char g_whi[NTILES * 8192];  // swizzled bf16 tiles
__device__ __align__(16) unsigned char g_wlo[NTILES * 8192];

// ---------------- helpers ----------------
static __device__ __forceinline__ uint32_t smem_u32(const void* p) {
    uint32_t a;
    asm("{ .reg .u64 t; cvta.to.shared.u64 t, %1; cvt.u32.u64 %0, t; }"
        : "=r"(a) : "l"(p));
    return a;
}
static __device__ __forceinline__ uint32_t swz(uint32_t o) {
    return o ^ ((o >> 3) & 0x70u);
}
static __device__ __forceinline__ void ldsm_x4(uint32_t& r0, uint32_t& r1, uint32_t& r2, uint32_t& r3, uint32_t addr) {
    asm volatile("ldmatrix.sync.aligned.m8n8.x4.shared.b16 {%0,%1,%2,%3}, [%4];"
                 : "=r"(r0), "=r"(r1), "=r"(r2), "=r"(r3) : "r"(addr));
}
static __device__ __forceinline__ void mma16816(float& c0, float& c1, float& c2, float& c3,
                                                uint32_t a0, uint32_t a1, uint32_t a2, uint32_t a3,
                                                uint32_t b0, uint32_t b1) {
    asm volatile("mma.sync.aligned.m16n8k16.row.col.f32.bf16.bf16.f32 "
                 "{%0,%1,%2,%3}, {%4,%5,%6,%7}, {%8,%9}, {%0,%1,%2,%3};"
                 : "+f"(c0), "+f"(c1), "+f"(c2), "+f"(c3)
                 : "r"(a0), "r"(a1), "r"(a2), "r"(a3), "r"(b0), "r"(b1));
}
static __device__ __forceinline__ void cp16(uint32_t dst, const void* src) {
    asm volatile("cp.async.cg.shared.global [%0], [%1], 16;" :: "r"(dst), "l"(src));
}
static __device__ __forceinline__ void cp_commit() {
    asm volatile("cp.async.commit_group;");
}
template<int N> static __device__ __forceinline__ void cp_wait() {
    asm volatile("cp.async.wait_group %0;" :: "n"(N));
}
static __device__ __forceinline__ float warp_red_sum32(float ss) {
    ss += __shfl_xor_sync(0xFFFFFFFFu, ss, 16);
    ss += __shfl_xor_sync(0xFFFFFFFFu, ss, 8);
    ss += __shfl_xor_sync(0xFFFFFFFFu, ss, 4);
    ss += __shfl_xor_sync(0xFFFFFFFFu, ss, 2);
    ss += __shfl_xor_sync(0xFFFFFFFFu, ss, 1);
    return ss;
}
static __device__ __forceinline__ void split_bf16(float a0, float a1, uint32_t& hp, uint32_t& lp) {
    __nv_bfloat16 h0 = __float2bfloat16(a0);
    __nv_bfloat16 h1 = __float2bfloat16(a1);
    __nv_bfloat16 l0 = __float2bfloat16(a0 - __bfloat162float(h0));
    __nv_bfloat16 l1 = __float2bfloat16(a1 - __bfloat162float(h1));
    hp = (uint32_t)__bfloat16_as_ushort(h0) | ((uint32_t)__bfloat16_as_ushort(h1) << 16);
    lp = (uint32_t)__bfloat16_as_ushort(l0) | ((uint32_t)__bfloat16_as_ushort(l1) << 16);
}

// ---------------- W prep (+ colmin/counter init): fp32 -> swizzled bf16 hi/lo + ||w||^2 ----------------
__global__ void prep_kernel(const float* __restrict__ W) {
    const int tile = blockIdx.x;             // 0..7
    const int tid = threadIdx.x;
    const int wid = tid >> 5;                // 8 warps x 8 rows
    const int lane = tid & 31;
    if (tile == 0) {                          // init colmin + done-counter
        g_colmin[tid]       = 0x7F800000;
        g_colmin[tid + 256] = 0x7F800000;
        if (tid == 0) g_ctr = 0;
    }
    float2 v[8];
#pragma unroll
    for (int r = 0; r < 8; r++) {
        int rl = wid * 8 + r;
        v[r] = *(const float2*)(W + (size_t)(tile * TN + rl) * DDIM + 2 * lane);
    }
#pragma unroll
    for (int r = 0; r < 8; r++) {
        int rl = wid * 8 + r;
        float ss = warp_red_sum32(v[r].x * v[r].x + v[r].y * v[r].y);
        if (lane == 0) g_w2[tile * TN + rl] = ss;
        uint32_t hp, lp;
        split_bf16(v[r].x, v[r].y, hp, lp);
        uint32_t off = (uint32_t)tile * 8192u + swz((uint32_t)(rl * 128 + lane * 4));
        *(uint32_t*)(g_whi + off) = hp;
        *(uint32_t*)(g_wlo + off) = lp;
    }
}

// ---------------- fused normalize + split-bf16 GEMM + distance-min ----------------
__global__ void __launch_bounds__(256, 3)
fused_kernel(const float* __restrict__ x, float* __restrict__ out) {
    extern __shared__ char smem[];
    const int tid  = threadIdx.x;
    const int wid  = tid >> 5;
    const int lane = tid & 31;
    const int m0   = blockIdx.x * TM;
    const uint32_t sb = smem_u32(smem);

    int*   rowmin_s = (int*)(smem + OFF_RMIN);
    int*   colmin_s = (int*)(smem + OFF_CMIN);
    float* w2s      = (float*)(smem + OFF_W2);

    // init smem scratch + load w2
    if (tid < 128) rowmin_s[tid] = 0x7F800000;
#pragma unroll
    for (int i = tid; i < KPROT; i += 256) {
        colmin_s[i] = 0x7F800000;
        w2s[i] = g_w2[i];
    }

    // prefetch W tile 0 into buffer 0
    {
        uint32_t dst = sb + OFF_WB + (uint32_t)tid * 16;
        cp16(dst,         g_whi + tid * 16);
        cp16(dst + 4096,  g_whi + 4096 + tid * 16);
        cp16(dst + 8192,  g_wlo + tid * 16);
        cp16(dst + 12288, g_wlo + 4096 + tid * 16);
        cp_commit();
    }

    // ---- A: load, normalize, write xn twice, split to swizzled bf16 hi/lo ----
    {
        float2 v[16];
        const float* xb = x + (size_t)(m0 + wid * 16) * DDIM + 2 * lane;
#pragma unroll
        for (int r = 0; r < 16; r++) v[r] = *(const float2*)(xb + r * DDIM);
        float* o0 = out + (size_t)(m0 + wid * 16) * DDIM + 2 * lane;
        float* o1 = o0 + XN1_OFF;
#pragma unroll
        for (int r = 0; r < 16; r++) {
            float ss = warp_red_sum32(v[r].x * v[r].x + v[r].y * v[r].y);
            float sc = 1.0f / fmaxf(sqrtf(ss), 1e-12f);
            float a0 = v[r].x * sc, a1 = v[r].y * sc;
            *(float2*)(o0 + r * DDIM) = make_float2(a0, a1);
            *(float2*)(o1 + r * DDIM) = make_float2(a0, a1);
            uint32_t hp, lp;
            split_bf16(a0, a1, hp, lp);
            uint32_t sw = swz((uint32_t)((wid * 16 + r) * 128 + lane * 4));
            *(uint32_t*)(smem + OFF_AHI + sw) = hp;
            *(uint32_t*)(smem + OFF_ALO + sw) = lp;
        }
    }

    // warp layout: 4(M) x 2(N); warp tile 32(M) x 32(N)
    const int wm = wid & 3;
    const int wn = wid >> 2;
    const int rr = lane >> 2;
    const int cc = (lane & 3) * 2;

    const uint32_t a_row  = (uint32_t)(wm * 32 + (lane & 7) + ((lane >> 3) & 1) * 8);
    const uint32_t a_kb   = (uint32_t)(((lane >> 4) & 1) * 16);
    const uint32_t b_row  = (uint32_t)(wn * 32 + (lane & 7) + ((lane >> 4) & 1) * 8);
    const uint32_t b_kb   = (uint32_t)(((lane >> 3) & 1) * 16);

    float rm[4];
#pragma unroll
    for (int s = 0; s < 4; s++) rm[s] = __int_as_float(0x7F800000);

    float* proto = out + PROTO_OFF;

    for (int t = 0; t < NTILES; t++) {
        cp_wait<0>();        // W tile t data has arrived
        __syncthreads();     // publish tile t; prove tile t-1 buffer drained
        if (t < NTILES - 1) {  // prefetch t+1 into the drained buffer (overlaps compute)
            uint32_t dst = sb + OFF_WB + (uint32_t)(((t + 1) & 1) * 16384) + (uint32_t)tid * 16;
            const unsigned char* sh = g_whi + (t + 1) * 8192 + tid * 16;
            const unsigned char* sl = g_wlo + (t + 1) * 8192 + tid * 16;
            cp16(dst, sh); cp16(dst + 4096, sh + 4096);
            cp16(dst + 8192, sl); cp16(dst + 12288, sl + 4096);
            cp_commit();
        }

        const uint32_t wb = sb + OFF_WB + (uint32_t)((t & 1) * 16384);

        float acc[2][4][4];
#pragma unroll
        for (int mb = 0; mb < 2; mb++)
#pragma unroll
            for (int nf = 0; nf < 4; nf++)
#pragma unroll
                for (int c = 0; c < 4; c++) acc[mb][nf][c] = 0.0f;

#pragma unroll
        for (int ks = 0; ks < 4; ks++) {
            const uint32_t koff = (uint32_t)(ks * 32);
            // B fragments: hi and lo, each 2 x ldsm_x4 (n16 x k16 per load)
            uint32_t bh[2][4], bl[2][4];
#pragma unroll
            for (int nb = 0; nb < 2; nb++) {
                uint32_t baddr = swz(((b_row + nb * 16) << 7) + koff + b_kb);
                ldsm_x4(bh[nb][0], bh[nb][1], bh[nb][2], bh[nb][3], wb + baddr);
                ldsm_x4(bl[nb][0], bl[nb][1], bl[nb][2], bl[nb][3], wb + 8192u + baddr);
            }
#pragma unroll
            for (int mb = 0; mb < 2; mb++) {
                uint32_t aaddr = swz(((a_row + mb * 16) << 7) + koff + a_kb);
                uint32_t ah0, ah1, ah2, ah3, al0, al1, al2, al3;
                ldsm_x4(ah0, ah1, ah2, ah3, sb + OFF_AHI + aaddr);
                ldsm_x4(al0, al1, al2, al3, sb + OFF_ALO + aaddr);
#pragma unroll
                for (int nb = 0; nb < 2; nb++) {
                    // hi x hi
                    mma16816(acc[mb][nb*2][0],   acc[mb][nb*2][1],   acc[mb][nb*2][2],   acc[mb][nb*2][3],
                             ah0, ah1, ah2, ah3, bh[nb][0], bh[nb][1]);
                    mma16816(acc[mb][nb*2+1][0], acc[mb][nb*2+1][1], acc[mb][nb*2+1][2], acc[mb][nb*2+1][3],
                             ah0, ah1, ah2, ah3, bh[nb][2], bh[nb][3]);
                    // hi x lo
                    mma16816(acc[mb][nb*2][0],   acc[mb][nb*2][1],   acc[mb][nb*2][2],   acc[mb][nb*2][3],
                             ah0, ah1, ah2, ah3, bl[nb][0], bl[nb][1]);
                    mma16816(acc[mb][nb*2+1][0], acc[mb][nb*2+1][1], acc[mb][nb*2+1][2], acc[mb][nb*2+1][3],
                             ah0, ah1, ah2, ah3, bl[nb][2], bl[nb][3]);
                    // lo x hi
                    mma16816(acc[mb][nb*2][0],   acc[mb][nb*2][1],   acc[mb][nb*2][2],   acc[mb][nb*2][3],
                             al0, al1, al2, al3, bh[nb][0], bh[nb][1]);
                    mma16816(acc[mb][nb*2+1][0], acc[mb][nb*2+1][1], acc[mb][nb*2+1][2], acc[mb][nb*2+1][3],
                             al0, al1, al2, al3, bh[nb][2], bh[nb][3]);
                }
            }
        }

        // ---- proto store directly from accumulators ----
#pragma unroll
        for (int mb = 0; mb < 2; mb++) {
            size_t rowg = (size_t)(m0 + wm * 32 + mb * 16 + rr);
            float* base = proto + rowg * KPROT + t * TN + wn * 32 + cc;
#pragma unroll
            for (int nf = 0; nf < 4; nf++) {
                *(float2*)(base + nf * 8)             = make_float2(acc[mb][nf][0], acc[mb][nf][1]);
                *(float2*)(base + nf * 8 + 8 * KPROT) = make_float2(acc[mb][nf][2], acc[mb][nf][3]);
            }
        }

        // ---- distance mins ----
#pragma unroll
        for (int nf = 0; nf < 4; nf++) {
            int colg = t * TN + wn * 32 + nf * 8 + cc;
            float w0 = 1.0f + w2s[colg];
            float w1 = 1.0f + w2s[colg + 1];
            float cm0 = __int_as_float(0x7F800000);
            float cm1 = cm0;
#pragma unroll
            for (int mb = 0; mb < 2; mb++) {
                float s0 = fmaf(-2.0f, acc[mb][nf][0], w0);
                float s1 = fmaf(-2.0f, acc[mb][nf][1], w1);
                float s2 = fmaf(-2.0f, acc[mb][nf][2], w0);
                float s3 = fmaf(-2.0f, acc[mb][nf][3], w1);
                rm[mb * 2]     = fminf(rm[mb * 2],     fminf(s0, s1));
                rm[mb * 2 + 1] = fminf(rm[mb * 2 + 1], fminf(s2, s3));
                cm0 = fminf(cm0, fminf(s0, s2));
                cm1 = fminf(cm1, fminf(s1, s3));
            }
            cm0 = fminf(cm0, __shfl_xor_sync(0xFFFFFFFFu, cm0, 4));
            cm0 = fminf(cm0, __shfl_xor_sync(0xFFFFFFFFu, cm0, 8));
            cm0 = fminf(cm0, __shfl_xor_sync(0xFFFFFFFFu, cm0, 16));
            cm1 = fminf(cm1, __shfl_xor_sync(0xFFFFFFFFu, cm1, 4));
            cm1 = fminf(cm1, __shfl_xor_sync(0xFFFFFFFFu, cm1, 8));
            cm1 = fminf(cm1, __shfl_xor_sync(0xFFFFFFFFu, cm1, 16));
            if (lane < 4) {
                atomicMin(&colmin_s[colg],     __float_as_int(fmaxf(cm0, 1e-12f)));
                atomicMin(&colmin_s[colg + 1], __float_as_int(fmaxf(cm1, 1e-12f)));
            }
        }
    }

    // ---- finalize row mins (register -> lane reduce -> smem -> global store) ----
#pragma unroll
    for (int s = 0; s < 4; s++) {
        rm[s] = fminf(rm[s], __shfl_xor_sync(0xFFFFFFFFu, rm[s], 1));
        rm[s] = fminf(rm[s], __shfl_xor_sync(0xFFFFFFFFu, rm[s], 2));
    }
    if ((lane & 3) == 0) {
#pragma unroll
        for (int s = 0; s < 4; s++) {
            int rl = wm * 32 + (s >> 1) * 16 + rr + (s & 1) * 8;
            atomicMin(&rowmin_s[rl], __float_as_int(fmaxf(rm[s], 1e-12f)));
        }
    }
    __syncthreads();
    if (tid < 128) g_rowmin[m0 + tid] = rowmin_s[tid];
#pragma unroll
    for (int i = tid; i < KPROT; i += 256)
        atomicMin(&g_colmin[i], colmin_s[i]);
}

// ---------------- deterministic reduction + finalize (last-block-done) ----------------
__global__ void reduce_kernel(const float* __restrict__ recon,
                              const float* __restrict__ kl,
                              const float* __restrict__ mmd,
                              float* __restrict__ outs) {
    __shared__ float red[256];
    __shared__ unsigned int s_last;
    int tid = threadIdx.x;
    int base = blockIdx.x * 1024;        // 128 blocks x 1024 rows
    float s = 0.0f;
#pragma unroll
    for (int j = 0; j < 4; j++) {
        int i = base + tid * 4 + j;
        s += sqrtf(fmaxf(__int_as_float(g_rowmin[i]), 1e-12f));
    }
    red[tid] = s;
    __syncthreads();
    for (int st = 128; st > 0; st >>= 1) { if (tid < st) red[tid] += red[tid + st]; __syncthreads(); }
    if (tid == 0) {
        g_partial[blockIdx.x] = red[0];
        __threadfence();
        s_last = atomicAdd(&g_ctr, 1u);
    }
    __syncthreads();

    if (s_last == 127) {                 // last block finalizes
        __threadfence();                 // acquire all g_partial writes
        float p = (tid < 128) ? g_partial[tid] : 0.0f;
        red[tid] = p;
        __syncthreads();
        for (int st = 128; st > 0; st >>= 1) { if (tid < st) red[tid] += red[tid + st]; __syncthreads(); }
        float rowsum = red[0];
        __syncthreads();

        float c = 0.0f;
#pragma unroll
        for (int j = 0; j < 2; j++)
            c += sqrtf(fmaxf(__int_as_float(g_colmin[tid * 2 + j]), 1e-12f));
        red[tid] = c;
        __syncthreads();
        for (int st = 128; st > 0; st >>= 1) { if (tid < st) red[tid] += red[tid + st]; __syncthreads(); }

        if (tid == 0) {
            float colsum = red[0];
            outs[0] = recon[0] + 0.5f * kl[0] + mmd[0];
            outs[1] = 0.5f * (rowsum * (1.0f / (float)NROWS))
                    + 0.5f * (colsum * (1.0f / (float)KPROT));
        }
    }
}

extern "C" void kernel_launch(void* const* d_in, const int* in_sizes, int n_in,
                              void* d_out, int out_size) {
    const float* x     = (const float*)d_in[0];
    const float* W     = (const float*)d_in[1];
    const float* recon = (const float*)d_in[2];
    const float* kl    = (const float*)d_in[3];
    const float* mmd   = (const float*)d_in[4];
    float* out = (float*)d_out;
    (void)in_sizes; (void)n_in; (void)out_size;

    cudaFuncSetAttribute(fused_kernel, cudaFuncAttributeMaxDynamicSharedMemorySize, SMEM_TOTAL);

    prep_kernel<<<NTILES, 256>>>(W);
    fused_kernel<<<NROWS / TM, 256, SMEM_TOTAL>>>(x, out);
    reduce_kernel<<<128, 256>>>(recon, kl, mmd, out + SCAL_OFF);
}

// round 14
// speedup vs baseline: 1.1492x; 1.1492x over previous
#include <cuda_runtime.h>
#include <cuda_fp16.h>
#include <stdint.h>

#define NROWS 131072
#define DDIM  64
#define KPROT 512
#define TM    128
#define TN    64
#define NTILES (KPROT / TN)   // 8

// ---- shared memory layout (bytes) ----
#define OFF_AHI   0        // 16KB  A hi (128 rows x 128B, swizzled fp16)
#define OFF_ALO   16384    // 16KB  A lo
#define OFF_WB    32768    // 2 x 8KB W hi double buffer (fp16)
#define OFF_W2    49152    // 512 floats (2KB)
#define OFF_RMIN  51200    // 128 ints
#define OFF_CMIN  51712    // 512 ints (2KB)
#define SMEM_TOTAL 53760

#define XN1_OFF   ((size_t)NROWS*DDIM)              // 8388608
#define PROTO_OFF ((size_t)2*NROWS*DDIM)            // 16777216
#define SCAL_OFF  (PROTO_OFF + (size_t)NROWS*KPROT) // 83886080

__device__ int          g_rowmin[NROWS];
__device__ int          g_colmin[KPROT];
__device__ float        g_partial[128];
__device__ float        g_w2[KPROT];
__device__ unsigned int g_ctr;
__device__ __align__(16) unsigned char g_whi[NTILES * 8192];  // swizzled fp16 W tiles

// ---------------- helpers ----------------
static __device__ __forceinline__ uint32_t smem_u32(const void* p) {
    uint32_t a;
    asm("{ .reg .u64 t; cvta.to.shared.u64 t, %1; cvt.u32.u64 %0, t; }"
        : "=r"(a) : "l"(p));
    return a;
}
static __device__ __forceinline__ uint32_t swz(uint32_t o) {
    return o ^ ((o >> 3) & 0x70u);
}
static __device__ __forceinline__ void ldsm_x4(uint32_t& r0, uint32_t& r1, uint32_t& r2, uint32_t& r3, uint32_t addr) {
    asm volatile("ldmatrix.sync.aligned.m8n8.x4.shared.b16 {%0,%1,%2,%3}, [%4];"
                 : "=r"(r0), "=r"(r1), "=r"(r2), "=r"(r3) : "r"(addr));
}
static __device__ __forceinline__ void mma16816(float& c0, float& c1, float& c2, float& c3,
                                                uint32_t a0, uint32_t a1, uint32_t a2, uint32_t a3,
                                                uint32_t b0, uint32_t b1) {
    asm volatile("mma.sync.aligned.m16n8k16.row.col.f32.f16.f16.f32 "
                 "{%0,%1,%2,%3}, {%4,%5,%6,%7}, {%8,%9}, {%0,%1,%2,%3};"
                 : "+f"(c0), "+f"(c1), "+f"(c2), "+f"(c3)
                 : "r"(a0), "r"(a1), "r"(a2), "r"(a3), "r"(b0), "r"(b1));
}
static __device__ __forceinline__ void cp16(uint32_t dst, const void* src) {
    asm volatile("cp.async.cg.shared.global [%0], [%1], 16;" :: "r"(dst), "l"(src));
}
static __device__ __forceinline__ void cp_commit() {
    asm volatile("cp.async.commit_group;");
}
template<int N> static __device__ __forceinline__ void cp_wait() {
    asm volatile("cp.async.wait_group %0;" :: "n"(N));
}
static __device__ __forceinline__ float warp_red_sum32(float ss) {
    ss += __shfl_xor_sync(0xFFFFFFFFu, ss, 16);
    ss += __shfl_xor_sync(0xFFFFFFFFu, ss, 8);
    ss += __shfl_xor_sync(0xFFFFFFFFu, ss, 4);
    ss += __shfl_xor_sync(0xFFFFFFFFu, ss, 2);
    ss += __shfl_xor_sync(0xFFFFFFFFu, ss, 1);
    return ss;
}
static __device__ __forceinline__ void split_fp16(float a0, float a1, uint32_t& hp, uint32_t& lp) {
    __half h0 = __float2half(a0);
    __half h1 = __float2half(a1);
    __half l0 = __float2half(a0 - __half2float(h0));
    __half l1 = __float2half(a1 - __half2float(h1));
    hp = (uint32_t)__half_as_ushort(h0) | ((uint32_t)__half_as_ushort(h1) << 16);
    lp = (uint32_t)__half_as_ushort(l0) | ((uint32_t)__half_as_ushort(l1) << 16);
}

// ---------------- W prep (+ colmin/counter init): fp32 -> swizzled fp16 hi + ||w||^2 ----------------
__global__ void prep_kernel(const float* __restrict__ W) {
    const int tile = blockIdx.x;             // 0..7
    const int tid = threadIdx.x;
    const int wid = tid >> 5;                // 8 warps x 8 rows
    const int lane = tid & 31;
    if (tile == 0) {                          // init colmin + done-counter
        g_colmin[tid]       = 0x7F800000;
        g_colmin[tid + 256] = 0x7F800000;
        if (tid == 0) g_ctr = 0;
    }
    float2 v[8];
#pragma unroll
    for (int r = 0; r < 8; r++) {
        int rl = wid * 8 + r;
        v[r] = *(const float2*)(W + (size_t)(tile * TN + rl) * DDIM + 2 * lane);
    }
#pragma unroll
    for (int r = 0; r < 8; r++) {
        int rl = wid * 8 + r;
        float ss = warp_red_sum32(v[r].x * v[r].x + v[r].y * v[r].y);
        if (lane == 0) g_w2[tile * TN + rl] = ss;
        uint32_t hp = (uint32_t)__half_as_ushort(__float2half(v[r].x))
                    | ((uint32_t)__half_as_ushort(__float2half(v[r].y)) << 16);
        uint32_t off = (uint32_t)tile * 8192u + swz((uint32_t)(rl * 128 + lane * 4));
        *(uint32_t*)(g_whi + off) = hp;
    }
}

// ---------------- fused normalize + 2-product fp16 GEMM + distance-min ----------------
__global__ void __launch_bounds__(256, 3)
fused_kernel(const float* __restrict__ x, float* __restrict__ out) {
    extern __shared__ char smem[];
    const int tid  = threadIdx.x;
    const int wid  = tid >> 5;
    const int lane = tid & 31;
    const int m0   = blockIdx.x * TM;
    const uint32_t sb = smem_u32(smem);

    int*   rowmin_s = (int*)(smem + OFF_RMIN);
    int*   colmin_s = (int*)(smem + OFF_CMIN);
    float* w2s      = (float*)(smem + OFF_W2);

    // init smem scratch + load w2
    if (tid < 128) rowmin_s[tid] = 0x7F800000;
#pragma unroll
    for (int i = tid; i < KPROT; i += 256) {
        colmin_s[i] = 0x7F800000;
        w2s[i] = g_w2[i];
    }

    // prefetch W tile 0 into buffer 0
    {
        uint32_t dst = sb + OFF_WB + (uint32_t)tid * 16;
        cp16(dst,        g_whi + tid * 16);
        cp16(dst + 4096, g_whi + 4096 + tid * 16);
        cp_commit();
    }

    // ---- A: load, normalize, write xn twice, split to swizzled fp16 hi/lo ----
    {
        float2 v[16];
        const float* xb = x + (size_t)(m0 + wid * 16) * DDIM + 2 * lane;
#pragma unroll
        for (int r = 0; r < 16; r++) v[r] = *(const float2*)(xb + r * DDIM);
        float* o0 = out + (size_t)(m0 + wid * 16) * DDIM + 2 * lane;
        float* o1 = o0 + XN1_OFF;
#pragma unroll
        for (int r = 0; r < 16; r++) {
            float ss = warp_red_sum32(v[r].x * v[r].x + v[r].y * v[r].y);
            float sc = 1.0f / fmaxf(sqrtf(ss), 1e-12f);
            float a0 = v[r].x * sc, a1 = v[r].y * sc;
            *(float2*)(o0 + r * DDIM) = make_float2(a0, a1);
            *(float2*)(o1 + r * DDIM) = make_float2(a0, a1);
            uint32_t hp, lp;
            split_fp16(a0, a1, hp, lp);
            uint32_t sw = swz((uint32_t)((wid * 16 + r) * 128 + lane * 4));
            *(uint32_t*)(smem + OFF_AHI + sw) = hp;
            *(uint32_t*)(smem + OFF_ALO + sw) = lp;
        }
    }

    // warp layout: 4(M) x 2(N); warp tile 32(M) x 32(N)
    const int wm = wid & 3;
    const int wn = wid >> 2;
    const int rr = lane >> 2;
    const int cc = (lane & 3) * 2;

    const uint32_t a_row  = (uint32_t)(wm * 32 + (lane & 7) + ((lane >> 3) & 1) * 8);
    const uint32_t a_kb   = (uint32_t)(((lane >> 4) & 1) * 16);
    const uint32_t b_row  = (uint32_t)(wn * 32 + (lane & 7) + ((lane >> 4) & 1) * 8);
    const uint32_t b_kb   = (uint32_t)(((lane >> 3) & 1) * 16);

    float rm[4];
#pragma unroll
    for (int s = 0; s < 4; s++) rm[s] = __int_as_float(0x7F800000);

    float* proto = out + PROTO_OFF;

    for (int t = 0; t < NTILES; t++) {
        cp_wait<0>();        // W tile t data has arrived
        __syncthreads();     // publish tile t; prove tile t-1 buffer drained
        if (t < NTILES - 1) {  // prefetch t+1 into the drained buffer (overlaps compute)
            uint32_t dst = sb + OFF_WB + (uint32_t)(((t + 1) & 1) * 8192) + (uint32_t)tid * 16;
            const unsigned char* sh = g_whi + (t + 1) * 8192 + tid * 16;
            cp16(dst, sh); cp16(dst + 4096, sh + 4096);
            cp_commit();
        }

        const uint32_t wb = sb + OFF_WB + (uint32_t)((t & 1) * 8192);

        float acc[2][4][4];
#pragma unroll
        for (int mb = 0; mb < 2; mb++)
#pragma unroll
            for (int nf = 0; nf < 4; nf++)
#pragma unroll
                for (int c = 0; c < 4; c++) acc[mb][nf][c] = 0.0f;

#pragma unroll
        for (int ks = 0; ks < 4; ks++) {
            const uint32_t koff = (uint32_t)(ks * 32);
            // B fragments: hi only (n16 x k16 per ldsm_x4)
            uint32_t bh[2][4];
#pragma unroll
            for (int nb = 0; nb < 2; nb++) {
                uint32_t baddr = swz(((b_row + nb * 16) << 7) + koff + b_kb);
                ldsm_x4(bh[nb][0], bh[nb][1], bh[nb][2], bh[nb][3], wb + baddr);
            }
#pragma unroll
            for (int mb = 0; mb < 2; mb++) {
                uint32_t aaddr = swz(((a_row + mb * 16) << 7) + koff + a_kb);
                uint32_t ah0, ah1, ah2, ah3, al0, al1, al2, al3;
                ldsm_x4(ah0, ah1, ah2, ah3, sb + OFF_AHI + aaddr);
                ldsm_x4(al0, al1, al2, al3, sb + OFF_ALO + aaddr);
#pragma unroll
                for (int nb = 0; nb < 2; nb++) {
                    // hi x hi
                    mma16816(acc[mb][nb*2][0],   acc[mb][nb*2][1],   acc[mb][nb*2][2],   acc[mb][nb*2][3],
                             ah0, ah1, ah2, ah3, bh[nb][0], bh[nb][1]);
                    mma16816(acc[mb][nb*2+1][0], acc[mb][nb*2+1][1], acc[mb][nb*2+1][2], acc[mb][nb*2+1][3],
                             ah0, ah1, ah2, ah3, bh[nb][2], bh[nb][3]);
                    // lo x hi
                    mma16816(acc[mb][nb*2][0],   acc[mb][nb*2][1],   acc[mb][nb*2][2],   acc[mb][nb*2][3],
                             al0, al1, al2, al3, bh[nb][0], bh[nb][1]);
                    mma16816(acc[mb][nb*2+1][0], acc[mb][nb*2+1][1], acc[mb][nb*2+1][2], acc[mb][nb*2+1][3],
                             al0, al1, al2, al3, bh[nb][2], bh[nb][3]);
                }
            }
        }

        // ---- proto store directly from accumulators ----
#pragma unroll
        for (int mb = 0; mb < 2; mb++) {
            size_t rowg = (size_t)(m0 + wm * 32 + mb * 16 + rr);
            float* base = proto + rowg * KPROT + t * TN + wn * 32 + cc;
#pragma unroll
            for (int nf = 0; nf < 4; nf++) {
                *(float2*)(base + nf * 8)             = make_float2(acc[mb][nf][0], acc[mb][nf][1]);
                *(float2*)(base + nf * 8 + 8 * KPROT) = make_float2(acc[mb][nf][2], acc[mb][nf][3]);
            }
        }

        // ---- distance mins ----
#pragma unroll
        for (int nf = 0; nf < 4; nf++) {
            int colg = t * TN + wn * 32 + nf * 8 + cc;
            float w0 = 1.0f + w2s[colg];
            float w1 = 1.0f + w2s[colg + 1];
            float cm0 = __int_as_float(0x7F800000);
            float cm1 = cm0;
#pragma unroll
            for (int mb = 0; mb < 2; mb++) {
                float s0 = fmaf(-2.0f, acc[mb][nf][0], w0);
                float s1 = fmaf(-2.0f, acc[mb][nf][1], w1);
                float s2 = fmaf(-2.0f, acc[mb][nf][2], w0);
                float s3 = fmaf(-2.0f, acc[mb][nf][3], w1);
                rm[mb * 2]     = fminf(rm[mb * 2],     fminf(s0, s1));
                rm[mb * 2 + 1] = fminf(rm[mb * 2 + 1], fminf(s2, s3));
                cm0 = fminf(cm0, fminf(s0, s2));
                cm1 = fminf(cm1, fminf(s1, s3));
            }
            cm0 = fminf(cm0, __shfl_xor_sync(0xFFFFFFFFu, cm0, 4));
            cm0 = fminf(cm0, __shfl_xor_sync(0xFFFFFFFFu, cm0, 8));
            cm0 = fminf(cm0, __shfl_xor_sync(0xFFFFFFFFu, cm0, 16));
            cm1 = fminf(cm1, __shfl_xor_sync(0xFFFFFFFFu, cm1, 4));
            cm1 = fminf(cm1, __shfl_xor_sync(0xFFFFFFFFu, cm1, 8));
            cm1 = fminf(cm1, __shfl_xor_sync(0xFFFFFFFFu, cm1, 16));
            if (lane < 4) {
                atomicMin(&colmin_s[colg],     __float_as_int(fmaxf(cm0, 1e-12f)));
                atomicMin(&colmin_s[colg + 1], __float_as_int(fmaxf(cm1, 1e-12f)));
            }
        }
    }

    // ---- finalize row mins (register -> lane reduce -> smem -> global store) ----
#pragma unroll
    for (int s = 0; s < 4; s++) {
        rm[s] = fminf(rm[s], __shfl_xor_sync(0xFFFFFFFFu, rm[s], 1));
        rm[s] = fminf(rm[s], __shfl_xor_sync(0xFFFFFFFFu, rm[s], 2));
    }
    if ((lane & 3) == 0) {
#pragma unroll
        for (int s = 0; s < 4; s++) {
            int rl = wm * 32 + (s >> 1) * 16 + rr + (s & 1) * 8;
            atomicMin(&rowmin_s[rl], __float_as_int(fmaxf(rm[s], 1e-12f)));
        }
    }
    __syncthreads();
    if (tid < 128) g_rowmin[m0 + tid] = rowmin_s[tid];
#pragma unroll
    for (int i = tid; i < KPROT; i += 256)
        atomicMin(&g_colmin[i], colmin_s[i]);
}

// ---------------- deterministic reduction + finalize (last-block-done) ----------------
__global__ void reduce_kernel(const float* __restrict__ recon,
                              const float* __restrict__ kl,
                              const float* __restrict__ mmd,
                              float* __restrict__ outs) {
    __shared__ float red[256];
    __shared__ unsigned int s_last;
    int tid = threadIdx.x;
    int base = blockIdx.x * 1024;        // 128 blocks x 1024 rows
    float s = 0.0f;
#pragma unroll
    for (int j = 0; j < 4; j++) {
        int i = base + tid * 4 + j;
        s += sqrtf(fmaxf(__int_as_float(g_rowmin[i]), 1e-12f));
    }
    red[tid] = s;
    __syncthreads();
    for (int st = 128; st > 0; st >>= 1) { if (tid < st) red[tid] += red[tid + st]; __syncthreads(); }
    if (tid == 0) {
        g_partial[blockIdx.x] = red[0];
        __threadfence();
        s_last = atomicAdd(&g_ctr, 1u);
    }
    __syncthreads();

    if (s_last == 127) {                 // last block finalizes
        __threadfence();                 // acquire all g_partial writes
        float p = (tid < 128) ? g_partial[tid] : 0.0f;
        red[tid] = p;
        __syncthreads();
        for (int st = 128; st > 0; st >>= 1) { if (tid < st) red[tid] += red[tid + st]; __syncthreads(); }
        float rowsum = red[0];
        __syncthreads();

        float c = 0.0f;
#pragma unroll
        for (int j = 0; j < 2; j++)
            c += sqrtf(fmaxf(__int_as_float(g_colmin[tid * 2 + j]), 1e-12f));
        red[tid] = c;
        __syncthreads();
        for (int st = 128; st > 0; st >>= 1) { if (tid < st) red[tid] += red[tid + st]; __syncthreads(); }

        if (tid == 0) {
            float colsum = red[0];
            outs[0] = recon[0] + 0.5f * kl[0] + mmd[0];
            outs[1] = 0.5f * (rowsum * (1.0f / (float)NROWS))
                    + 0.5f * (colsum * (1.0f / (float)KPROT));
        }
    }
}

extern "C" void kernel_launch(void* const* d_in, const int* in_sizes, int n_in,
                              void* d_out, int out_size) {
    const float* x     = (const float*)d_in[0];
    const float* W     = (const float*)d_in[1];
    const float* recon = (const float*)d_in[2];
    const float* kl    = (const float*)d_in[3];
    const float* mmd   = (const float*)d_in[4];
    float* out = (float*)d_out;
    (void)in_sizes; (void)n_in; (void)out_size;

    cudaFuncSetAttribute(fused_kernel, cudaFuncAttributeMaxDynamicSharedMemorySize, SMEM_TOTAL);

    prep_kernel<<<NTILES, 256>>>(W);
    fused_kernel<<<NROWS / TM, 256, SMEM_TOTAL>>>(x, out);
    reduce_kernel<<<128, 256>>>(recon, kl, mmd, out + SCAL_OFF);
}

// round 15
// speedup vs baseline: 1.3423x; 1.1680x over previous
#include <cuda_runtime.h>
#include <cuda_fp16.h>
#include <stdint.h>

#define NROWS 131072
#define DDIM  64
#define KPROT 512
#define TM    128
#define TN    64
#define NTILES (KPROT / TN)   // 8

// ---- shared memory layout (bytes) ----
#define OFF_AHI   0        // 16KB  A (128 rows x 128B, swizzled fp16)
#define OFF_WB    16384    // 2 x 8KB W double buffer (fp16)
#define OFF_W2    32768    // 512 floats (2KB)
#define OFF_RMIN  34816    // 128 ints
#define OFF_CMIN  35328    // 512 ints (2KB)
#define SMEM_TOTAL 37376

#define XN1_OFF   ((size_t)NROWS*DDIM)              // 8388608
#define PROTO_OFF ((size_t)2*NROWS*DDIM)            // 16777216
#define SCAL_OFF  (PROTO_OFF + (size_t)NROWS*KPROT) // 83886080

__device__ int          g_rowmin[NROWS];
__device__ int          g_colmin[KPROT];
__device__ float        g_partial[128];
__device__ float        g_w2[KPROT];
__device__ unsigned int g_ctr;
__device__ __align__(16) unsigned char g_whi[NTILES * 8192];  // swizzled fp16 W tiles

// ---------------- helpers ----------------
static __device__ __forceinline__ uint32_t smem_u32(const void* p) {
    uint32_t a;
    asm("{ .reg .u64 t; cvta.to.shared.u64 t, %1; cvt.u32.u64 %0, t; }"
        : "=r"(a) : "l"(p));
    return a;
}
static __device__ __forceinline__ uint32_t swz(uint32_t o) {
    return o ^ ((o >> 3) & 0x70u);
}
static __device__ __forceinline__ void ldsm_x4(uint32_t& r0, uint32_t& r1, uint32_t& r2, uint32_t& r3, uint32_t addr) {
    asm volatile("ldmatrix.sync.aligned.m8n8.x4.shared.b16 {%0,%1,%2,%3}, [%4];"
                 : "=r"(r0), "=r"(r1), "=r"(r2), "=r"(r3) : "r"(addr));
}
static __device__ __forceinline__ void mma16816(float& c0, float& c1, float& c2, float& c3,
                                                uint32_t a0, uint32_t a1, uint32_t a2, uint32_t a3,
                                                uint32_t b0, uint32_t b1) {
    asm volatile("mma.sync.aligned.m16n8k16.row.col.f32.f16.f16.f32 "
                 "{%0,%1,%2,%3}, {%4,%5,%6,%7}, {%8,%9}, {%0,%1,%2,%3};"
                 : "+f"(c0), "+f"(c1), "+f"(c2), "+f"(c3)
                 : "r"(a0), "r"(a1), "r"(a2), "r"(a3), "r"(b0), "r"(b1));
}
static __device__ __forceinline__ void cp16(uint32_t dst, const void* src) {
    asm volatile("cp.async.cg.shared.global [%0], [%1], 16;" :: "r"(dst), "l"(src));
}
static __device__ __forceinline__ void cp_commit() {
    asm volatile("cp.async.commit_group;");
}
template<int N> static __device__ __forceinline__ void cp_wait() {
    asm volatile("cp.async.wait_group %0;" :: "n"(N));
}
static __device__ __forceinline__ float warp_red_sum32(float ss) {
    ss += __shfl_xor_sync(0xFFFFFFFFu, ss, 16);
    ss += __shfl_xor_sync(0xFFFFFFFFu, ss, 8);
    ss += __shfl_xor_sync(0xFFFFFFFFu, ss, 4);
    ss += __shfl_xor_sync(0xFFFFFFFFu, ss, 2);
    ss += __shfl_xor_sync(0xFFFFFFFFu, ss, 1);
    return ss;
}

// ---------------- W prep (+ colmin/counter init): fp32 -> swizzled fp16 + ||w||^2 ----------------
__global__ void prep_kernel(const float* __restrict__ W) {
    const int tile = blockIdx.x;             // 0..7
    const int tid = threadIdx.x;
    const int wid = tid >> 5;                // 8 warps x 8 rows
    const int lane = tid & 31;
    if (tile == 0) {                          // init colmin + done-counter
        g_colmin[tid]       = 0x7F800000;
        g_colmin[tid + 256] = 0x7F800000;
        if (tid == 0) g_ctr = 0;
    }
    float2 v[8];
#pragma unroll
    for (int r = 0; r < 8; r++) {
        int rl = wid * 8 + r;
        v[r] = *(const float2*)(W + (size_t)(tile * TN + rl) * DDIM + 2 * lane);
    }
#pragma unroll
    for (int r = 0; r < 8; r++) {
        int rl = wid * 8 + r;
        float ss = warp_red_sum32(v[r].x * v[r].x + v[r].y * v[r].y);
        if (lane == 0) g_w2[tile * TN + rl] = ss;
        uint32_t hp = (uint32_t)__half_as_ushort(__float2half(v[r].x))
                    | ((uint32_t)__half_as_ushort(__float2half(v[r].y)) << 16);
        uint32_t off = (uint32_t)tile * 8192u + swz((uint32_t)(rl * 128 + lane * 4));
        *(uint32_t*)(g_whi + off) = hp;
    }
}

// ---------------- fused normalize + single-product fp16 GEMM + distance-min ----------------
__global__ void __launch_bounds__(256, 3)
fused_kernel(const float* __restrict__ x, float* __restrict__ out) {
    extern __shared__ char smem[];
    const int tid  = threadIdx.x;
    const int wid  = tid >> 5;
    const int lane = tid & 31;
    const int m0   = blockIdx.x * TM;
    const uint32_t sb = smem_u32(smem);

    int*   rowmin_s = (int*)(smem + OFF_RMIN);
    int*   colmin_s = (int*)(smem + OFF_CMIN);
    float* w2s      = (float*)(smem + OFF_W2);

    // init smem scratch + load w2
    if (tid < 128) rowmin_s[tid] = 0x7F800000;
#pragma unroll
    for (int i = tid; i < KPROT; i += 256) {
        colmin_s[i] = 0x7F800000;
        w2s[i] = g_w2[i];
    }

    // prefetch W tile 0 into buffer 0
    {
        uint32_t dst = sb + OFF_WB + (uint32_t)tid * 16;
        cp16(dst,        g_whi + tid * 16);
        cp16(dst + 4096, g_whi + 4096 + tid * 16);
        cp_commit();
    }

    // ---- A: load, normalize, write xn twice, round to swizzled fp16 ----
    {
        float2 v[16];
        const float* xb = x + (size_t)(m0 + wid * 16) * DDIM + 2 * lane;
#pragma unroll
        for (int r = 0; r < 16; r++) v[r] = *(const float2*)(xb + r * DDIM);
        float* o0 = out + (size_t)(m0 + wid * 16) * DDIM + 2 * lane;
        float* o1 = o0 + XN1_OFF;
#pragma unroll
        for (int r = 0; r < 16; r++) {
            float ss = warp_red_sum32(v[r].x * v[r].x + v[r].y * v[r].y);
            float sc = 1.0f / fmaxf(sqrtf(ss), 1e-12f);
            float a0 = v[r].x * sc, a1 = v[r].y * sc;
            *(float2*)(o0 + r * DDIM) = make_float2(a0, a1);
            *(float2*)(o1 + r * DDIM) = make_float2(a0, a1);
            uint32_t hp = (uint32_t)__half_as_ushort(__float2half(a0))
                        | ((uint32_t)__half_as_ushort(__float2half(a1)) << 16);
            uint32_t sw = swz((uint32_t)((wid * 16 + r) * 128 + lane * 4));
            *(uint32_t*)(smem + OFF_AHI + sw) = hp;
        }
    }

    // warp layout: 4(M) x 2(N); warp tile 32(M) x 32(N)
    const int wm = wid & 3;
    const int wn = wid >> 2;
    const int rr = lane >> 2;
    const int cc = (lane & 3) * 2;

    const uint32_t a_row  = (uint32_t)(wm * 32 + (lane & 7) + ((lane >> 3) & 1) * 8);
    const uint32_t a_kb   = (uint32_t)(((lane >> 4) & 1) * 16);
    const uint32_t b_row  = (uint32_t)(wn * 32 + (lane & 7) + ((lane >> 4) & 1) * 8);
    const uint32_t b_kb   = (uint32_t)(((lane >> 3) & 1) * 16);

    float rm[4];
#pragma unroll
    for (int s = 0; s < 4; s++) rm[s] = __int_as_float(0x7F800000);

    float* proto = out + PROTO_OFF;

    for (int t = 0; t < NTILES; t++) {
        cp_wait<0>();        // W tile t data has arrived
        __syncthreads();     // publish tile t; prove tile t-1 buffer drained
        if (t < NTILES - 1) {  // prefetch t+1 into the drained buffer (overlaps compute)
            uint32_t dst = sb + OFF_WB + (uint32_t)(((t + 1) & 1) * 8192) + (uint32_t)tid * 16;
            const unsigned char* sh = g_whi + (t + 1) * 8192 + tid * 16;
            cp16(dst, sh); cp16(dst + 4096, sh + 4096);
            cp_commit();
        }

        const uint32_t wb = sb + OFF_WB + (uint32_t)((t & 1) * 8192);

        float acc[2][4][4];
#pragma unroll
        for (int mb = 0; mb < 2; mb++)
#pragma unroll
            for (int nf = 0; nf < 4; nf++)
#pragma unroll
                for (int c = 0; c < 4; c++) acc[mb][nf][c] = 0.0f;

#pragma unroll
        for (int ks = 0; ks < 4; ks++) {
            const uint32_t koff = (uint32_t)(ks * 32);
            // B fragments (n16 x k16 per ldsm_x4)
            uint32_t bh[2][4];
#pragma unroll
            for (int nb = 0; nb < 2; nb++) {
                uint32_t baddr = swz(((b_row + nb * 16) << 7) + koff + b_kb);
                ldsm_x4(bh[nb][0], bh[nb][1], bh[nb][2], bh[nb][3], wb + baddr);
            }
#pragma unroll
            for (int mb = 0; mb < 2; mb++) {
                uint32_t aaddr = swz(((a_row + mb * 16) << 7) + koff + a_kb);
                uint32_t ah0, ah1, ah2, ah3;
                ldsm_x4(ah0, ah1, ah2, ah3, sb + OFF_AHI + aaddr);
#pragma unroll
                for (int nb = 0; nb < 2; nb++) {
                    mma16816(acc[mb][nb*2][0],   acc[mb][nb*2][1],   acc[mb][nb*2][2],   acc[mb][nb*2][3],
                             ah0, ah1, ah2, ah3, bh[nb][0], bh[nb][1]);
                    mma16816(acc[mb][nb*2+1][0], acc[mb][nb*2+1][1], acc[mb][nb*2+1][2], acc[mb][nb*2+1][3],
                             ah0, ah1, ah2, ah3, bh[nb][2], bh[nb][3]);
                }
            }
        }

        // ---- proto store directly from accumulators ----
#pragma unroll
        for (int mb = 0; mb < 2; mb++) {
            size_t rowg = (size_t)(m0 + wm * 32 + mb * 16 + rr);
            float* base = proto + rowg * KPROT + t * TN + wn * 32 + cc;
#pragma unroll
            for (int nf = 0; nf < 4; nf++) {
                *(float2*)(base + nf * 8)             = make_float2(acc[mb][nf][0], acc[mb][nf][1]);
                *(float2*)(base + nf * 8 + 8 * KPROT) = make_float2(acc[mb][nf][2], acc[mb][nf][3]);
            }
        }

        // ---- distance mins ----
#pragma unroll
        for (int nf = 0; nf < 4; nf++) {
            int colg = t * TN + wn * 32 + nf * 8 + cc;
            float w0 = 1.0f + w2s[colg];
            float w1 = 1.0f + w2s[colg + 1];
            float cm0 = __int_as_float(0x7F800000);
            float cm1 = cm0;
#pragma unroll
            for (int mb = 0; mb < 2; mb++) {
                float s0 = fmaf(-2.0f, acc[mb][nf][0], w0);
                float s1 = fmaf(-2.0f, acc[mb][nf][1], w1);
                float s2 = fmaf(-2.0f, acc[mb][nf][2], w0);
                float s3 = fmaf(-2.0f, acc[mb][nf][3], w1);
                rm[mb * 2]     = fminf(rm[mb * 2],     fminf(s0, s1));
                rm[mb * 2 + 1] = fminf(rm[mb * 2 + 1], fminf(s2, s3));
                cm0 = fminf(cm0, fminf(s0, s2));
                cm1 = fminf(cm1, fminf(s1, s3));
            }
            cm0 = fminf(cm0, __shfl_xor_sync(0xFFFFFFFFu, cm0, 4));
            cm0 = fminf(cm0, __shfl_xor_sync(0xFFFFFFFFu, cm0, 8));
            cm0 = fminf(cm0, __shfl_xor_sync(0xFFFFFFFFu, cm0, 16));
            cm1 = fminf(cm1, __shfl_xor_sync(0xFFFFFFFFu, cm1, 4));
            cm1 = fminf(cm1, __shfl_xor_sync(0xFFFFFFFFu, cm1, 8));
            cm1 = fminf(cm1, __shfl_xor_sync(0xFFFFFFFFu, cm1, 16));
            if (lane < 4) {
                atomicMin(&colmin_s[colg],     __float_as_int(fmaxf(cm0, 1e-12f)));
                atomicMin(&colmin_s[colg + 1], __float_as_int(fmaxf(cm1, 1e-12f)));
            }
        }
    }

    // ---- finalize row mins (register -> lane reduce -> smem -> global store) ----
#pragma unroll
    for (int s = 0; s < 4; s++) {
        rm[s] = fminf(rm[s], __shfl_xor_sync(0xFFFFFFFFu, rm[s], 1));
        rm[s] = fminf(rm[s], __shfl_xor_sync(0xFFFFFFFFu, rm[s], 2));
    }
    if ((lane & 3) == 0) {
#pragma unroll
        for (int s = 0; s < 4; s++) {
            int rl = wm * 32 + (s >> 1) * 16 + rr + (s & 1) * 8;
            atomicMin(&rowmin_s[rl], __float_as_int(fmaxf(rm[s], 1e-12f)));
        }
    }
    __syncthreads();
    if (tid < 128) g_rowmin[m0 + tid] = rowmin_s[tid];
#pragma unroll
    for (int i = tid; i < KPROT; i += 256)
        atomicMin(&g_colmin[i], colmin_s[i]);
}

// ---------------- deterministic reduction + finalize (last-block-done) ----------------
__global__ void reduce_kernel(const float* __restrict__ recon,
                              const float* __restrict__ kl,
                              const float* __restrict__ mmd,
                              float* __restrict__ outs) {
    __shared__ float red[256];
    __shared__ unsigned int s_last;
    int tid = threadIdx.x;
    int base = blockIdx.x * 1024;        // 128 blocks x 1024 rows
    float s = 0.0f;
#pragma unroll
    for (int j = 0; j < 4; j++) {
        int i = base + tid * 4 + j;
        s += sqrtf(fmaxf(__int_as_float(g_rowmin[i]), 1e-12f));
    }
    red[tid] = s;
    __syncthreads();
    for (int st = 128; st > 0; st >>= 1) { if (tid < st) red[tid] += red[tid + st]; __syncthreads(); }
    if (tid == 0) {
        g_partial[blockIdx.x] = red[0];
        __threadfence();
        s_last = atomicAdd(&g_ctr, 1u);
    }
    __syncthreads();

    if (s_last == 127) {                 // last block finalizes
        __threadfence();                 // acquire all g_partial writes
        float p = (tid < 128) ? g_partial[tid] : 0.0f;
        red[tid] = p;
        __syncthreads();
        for (int st = 128; st > 0; st >>= 1) { if (tid < st) red[tid] += red[tid + st]; __syncthreads(); }
        float rowsum = red[0];
        __syncthreads();

        float c = 0.0f;
#pragma unroll
        for (int j = 0; j < 2; j++)
            c += sqrtf(fmaxf(__int_as_float(g_colmin[tid * 2 + j]), 1e-12f));
        red[tid] = c;
        __syncthreads();
        for (int st = 128; st > 0; st >>= 1) { if (tid < st) red[tid] += red[tid + st]; __syncthreads(); }

        if (tid == 0) {
            float colsum = red[0];
            outs[0] = recon[0] + 0.5f * kl[0] + mmd[0];
            outs[1] = 0.5f * (rowsum * (1.0f / (float)NROWS))
                    + 0.5f * (colsum * (1.0f / (float)KPROT));
        }
    }
}

extern "C" void kernel_launch(void* const* d_in, const int* in_sizes, int n_in,
                              void* d_out, int out_size) {
    const float* x     = (const float*)d_in[0];
    const float* W     = (const float*)d_in[1];
    const float* recon = (const float*)d_in[2];
    const float* kl    = (const float*)d_in[3];
    const float* mmd   = (const float*)d_in[4];
    float* out = (float*)d_out;
    (void)in_sizes; (void)n_in; (void)out_size;

    cudaFuncSetAttribute(fused_kernel, cudaFuncAttributeMaxDynamicSharedMemorySize, SMEM_TOTAL);

    prep_kernel<<<NTILES, 256>>>(W);
    fused_kernel<<<NROWS / TM, 256, SMEM_TOTAL>>>(x, out);
    reduce_kernel<<<128, 256>>>(recon, kl, mmd, out + SCAL_OFF);
}